// round 2
// baseline (speedup 1.0000x reference)
#include <cuda_runtime.h>
#include <cuda_bf16.h>
#include <mma.h>

using namespace nvcuda;

// ---------------- problem constants ----------------
#define TT   128      // seq len
#define BB   64       // batch
#define HH   512      // hidden
#define VV   10000    // vocab

// fused K' for split-bf16 gemm: [Ahi | Alo | Ahi] @ [[Bhi];[Bhi];[Blo]]
#define KP   1536
#define VPAD 10112    // 79 * 128

// output layout: logits (T*B, V), then state (B,H), then cell (B,H)
#define OUT_STATE_OFF 81920000u
#define OUT_CELL_OFF  81952768u

// ---------------- device scratch (no allocation allowed) ----------------
__device__ float          g_WT[4][HH][HH];            // transposed hidden weights, 4 MB
__device__ float          g_Hall[TT * BB * HH];       // all hidden states, 16 MB
__device__ __nv_bfloat16  g_A2[(size_t)TT * BB * KP]; // split A, 24 MB
__device__ __nv_bfloat16  g_B2[(size_t)KP * VPAD];    // split B, ~31 MB
__device__ unsigned       g_cnt = 0;
__device__ unsigned       g_gen = 0;

__device__ __forceinline__ float sigmoidf_(float x) {
    return 1.0f / (1.0f + expf(-x));
}

// ---------------- prep: transpose the 4 hidden weight matrices ----------------
// WT[g][j][k] = W_g[k][j]  (so a gate column is a contiguous 512-float row)
__global__ void build_wt(const float* __restrict__ Wi, const float* __restrict__ Wf,
                         const float* __restrict__ Wo, const float* __restrict__ Wc) {
    int idx = blockIdx.x * blockDim.x + threadIdx.x;
    if (idx >= 4 * HH * HH) return;
    int g   = idx >> 18;
    int rem = idx & 262143;
    int j   = rem >> 9;
    int k   = rem & 511;
    const float* W = (g == 0) ? Wi : (g == 1) ? Wf : (g == 2) ? Wo : Wc;
    g_WT[g][j][k] = W[k * HH + j];
}

// ---------------- prep: split W_hq into bf16 hi/lo, padded to VPAD ----------------
__global__ void build_b2(const float* __restrict__ Whq) {
    int idx = blockIdx.x * blockDim.x + threadIdx.x;
    if (idx >= KP * VPAD) return;
    int r = idx / VPAD;
    int n = idx - r * VPAD;
    __nv_bfloat16 v;
    if (n >= VV) {
        v = __float2bfloat16(0.0f);
    } else {
        int rr  = r & 511;
        int reg = r >> 9;            // 0:hi  1:hi  2:lo
        float w = Whq[rr * VV + n];
        __nv_bfloat16 hi = __float2bfloat16(w);
        v = (reg < 2) ? hi : __float2bfloat16(w - __bfloat162float(hi));
    }
    g_B2[idx] = v;
}

// ---------------- prep: split H_all into bf16 hi/lo ----------------
__global__ void build_a2() {
    int idx = blockIdx.x * blockDim.x + threadIdx.x;
    if (idx >= TT * BB * KP) return;
    int m  = idx / KP;
    int kp = idx - m * KP;
    int reg = kp >> 9;               // 0:hi 1:lo 2:hi
    int k   = kp & 511;
    float v = g_Hall[m * HH + k];
    __nv_bfloat16 hi = __float2bfloat16(v);
    g_A2[idx] = (reg == 1) ? __float2bfloat16(v - __bfloat162float(hi)) : hi;
}

// ---------------- persistent sequential LSTM recurrence ----------------
// grid = 128 CTAs (4 batch-tiles x 32 hidden-chunks), 256 threads
// CTA(bt,hc): batch rows [bt*16, bt*16+16), hidden units [hc*16, hc*16+16)
//   -> 64 weight columns (16 units x 4 gates) pinned in SMEM for all 128 steps.
// cell state lives in SMEM for the whole sequence.
#define WSTRIDE 516  // 512 + 4 pad (bank-conflict mitigation)

__global__ void __launch_bounds__(256, 1)
lstm_steps(const int* __restrict__ x,
           const float* __restrict__ state0, const float* __restrict__ cell0,
           const float* __restrict__ Wxi, const float* __restrict__ Wxf,
           const float* __restrict__ Wxo, const float* __restrict__ Wxc,
           const float* __restrict__ bi,  const float* __restrict__ bf_,
           const float* __restrict__ bo,  const float* __restrict__ bc,
           float* __restrict__ out) {
    extern __shared__ float sm[];
    float* Wseg = sm;                       // 64 * 516
    float* hbuf = Wseg + 64 * WSTRIDE;      // 16 * 512
    float* gbuf = hbuf + 16 * 512;          // 4 * 16 * 16
    float* cbuf = gbuf + 1024;              // 16 * 16

    const int tid = threadIdx.x;
    const int bt  = blockIdx.x & 3;         // batch tile
    const int hc  = blockIdx.x >> 2;        // hidden chunk
    const int c   = tid & 63;               // weight column 0..63
    const int rg  = tid >> 6;               // row group 0..3 (4 rows each)
    const int g   = c >> 4;                 // gate: 0=i 1=f 2=o 3=g
    const int u   = c & 15;                 // local hidden unit
    const int j   = hc * 16 + u;            // global hidden unit

    unsigned genBase = 0;
    if (tid == 0) genBase = *(volatile unsigned*)&g_gen;  // stable: no bump until all arrive

    // pin this CTA's weight columns in SMEM (reused for all 128 steps)
    for (int idx = tid; idx < 64 * 512; idx += 256) {
        int cc = idx >> 9, kk = idx & 511;
        int gg = cc >> 4, uu = cc & 15;
        Wseg[cc * WSTRIDE + kk] = g_WT[gg][hc * 16 + uu][kk];
    }
    // cell state -> SMEM
    {
        int bl = tid >> 4, uu = tid & 15;
        cbuf[bl * 16 + uu] = cell0[(bt * 16 + bl) * HH + hc * 16 + uu];
    }
    const float* bptr = (g == 0) ? bi : (g == 1) ? bf_ : (g == 2) ? bo : bc;
    const float  bias = bptr[j];
    const float* Wx   = (g == 0) ? Wxi : (g == 1) ? Wxf : (g == 2) ? Wxo : Wxc;
    __syncthreads();

    for (int t = 0; t < TT; t++) {
        // stage h_{t-1} rows for this batch tile
        const float* hp = (t == 0) ? state0 : (g_Hall + (t - 1) * BB * HH);
        for (int idx = tid; idx < 16 * 512; idx += 256) {
            int bl = idx >> 9, kk = idx & 511;
            hbuf[bl * 512 + kk] = hp[(bt * 16 + bl) * HH + kk];
        }
        __syncthreads();

        // 4-row x 1-col register tile, K=512 dot products from SMEM
        float acc0 = 0.f, acc1 = 0.f, acc2 = 0.f, acc3 = 0.f;
        const float* wrow = Wseg + c * WSTRIDE;
        const float* h0 = hbuf + (rg * 4 + 0) * 512;
        const float* h1 = hbuf + (rg * 4 + 1) * 512;
        const float* h2 = hbuf + (rg * 4 + 2) * 512;
        const float* h3 = hbuf + (rg * 4 + 3) * 512;
        #pragma unroll 8
        for (int kk = 0; kk < 512; kk += 4) {
            float4 w = *reinterpret_cast<const float4*>(wrow + kk);
            float4 a = *reinterpret_cast<const float4*>(h0 + kk);
            acc0 = fmaf(w.x, a.x, acc0); acc0 = fmaf(w.y, a.y, acc0);
            acc0 = fmaf(w.z, a.z, acc0); acc0 = fmaf(w.w, a.w, acc0);
            a = *reinterpret_cast<const float4*>(h1 + kk);
            acc1 = fmaf(w.x, a.x, acc1); acc1 = fmaf(w.y, a.y, acc1);
            acc1 = fmaf(w.z, a.z, acc1); acc1 = fmaf(w.w, a.w, acc1);
            a = *reinterpret_cast<const float4*>(h2 + kk);
            acc2 = fmaf(w.x, a.x, acc2); acc2 = fmaf(w.y, a.y, acc2);
            acc2 = fmaf(w.z, a.z, acc2); acc2 = fmaf(w.w, a.w, acc2);
            a = *reinterpret_cast<const float4*>(h3 + kk);
            acc3 = fmaf(w.x, a.x, acc3); acc3 = fmaf(w.y, a.y, acc3);
            acc3 = fmaf(w.z, a.z, acc3); acc3 = fmaf(w.w, a.w, acc3);
        }

        // add bias + token-row gather, apply activation, publish to gate buffer
        float accs[4] = {acc0, acc1, acc2, acc3};
        #pragma unroll
        for (int r = 0; r < 4; r++) {
            int b   = bt * 16 + rg * 4 + r;
            int tok = x[b * TT + t];
            float pre = accs[r] + bias + Wx[tok * HH + j];
            float act = (g < 3) ? sigmoidf_(pre) : tanhf(pre);
            gbuf[g * 256 + (rg * 4 + r) * 16 + u] = act;
        }
        __syncthreads();

        // c/h update for this CTA's (16 rows x 16 units) patch
        {
            int bl = tid >> 4, uu = tid & 15;
            int o  = bl * 16 + uu;
            float iv = gbuf[o];
            float fv = gbuf[256 + o];
            float ov = gbuf[512 + o];
            float gv = gbuf[768 + o];
            float cn = fmaf(fv, cbuf[o], iv * gv);
            cbuf[o] = cn;
            float hn = ov * tanhf(cn);
            int brow = bt * 16 + bl, kcol = hc * 16 + uu;
            g_Hall[(t * BB + brow) * HH + kcol] = hn;
            if (t == TT - 1) {
                out[OUT_STATE_OFF + brow * HH + kcol] = hn;
                out[OUT_CELL_OFF  + brow * HH + kcol] = cn;
            }
        }
        __threadfence();
        __syncthreads();

        // software grid barrier (128 CTAs, single wave guaranteed)
        if (t < TT - 1) {
            if (tid == 0) {
                unsigned arr = atomicAdd(&g_cnt, 1u);
                if (arr == gridDim.x - 1) {
                    atomicExch(&g_cnt, 0u);
                    __threadfence();
                    atomicAdd(&g_gen, 1u);
                } else {
                    unsigned target = (unsigned)(t + 1);
                    while ((*(volatile unsigned*)&g_gen) - genBase < target)
                        __nanosleep(40);
                }
                __threadfence();
            }
            __syncthreads();
        }
    }
}

// ---------------- split-bf16 output GEMM: out = A2 @ B2 + b_q ----------------
// C(8192 x 10000) staged as 128x128 tiles, K' = 1536, wmma bf16 (fp32 accum)
#define GBM 128
#define GBN 128
#define GBK 32
#define ALD 40    // As leading dim (bf16)
#define BLD 136   // Bs leading dim (bf16)
#define CLD 132   // Cs leading dim (f32)

__global__ void __launch_bounds__(256)
gemm_out(const float* __restrict__ bq, float* __restrict__ out) {
    extern __shared__ char smraw[];
    __nv_bfloat16* As = reinterpret_cast<__nv_bfloat16*>(smraw);
    __nv_bfloat16* Bs = reinterpret_cast<__nv_bfloat16*>(smraw + GBM * ALD * 2);
    float*         Cs = reinterpret_cast<float*>(smraw);   // reused after compute

    const int m0  = blockIdx.y * GBM;
    const int n0  = blockIdx.x * GBN;
    const int tid = threadIdx.x;
    const int warp = tid >> 5;
    const int wr = warp >> 1;   // 0..3  -> 32 rows each
    const int wc = warp & 1;    // 0..1  -> 64 cols each

    wmma::fragment<wmma::accumulator, 16, 16, 16, float> acc[2][4];
    #pragma unroll
    for (int i = 0; i < 2; i++)
        #pragma unroll
        for (int jn = 0; jn < 4; jn++)
            wmma::fill_fragment(acc[i][jn], 0.0f);

    for (int k0 = 0; k0 < KP; k0 += GBK) {
        // A tile 128x32 (8 bf16 per int4 chunk)
        #pragma unroll
        for (int cch = tid; cch < 512; cch += 256) {
            int row = cch >> 2, col = (cch & 3) * 8;
            *reinterpret_cast<int4*>(&As[row * ALD + col]) =
                *reinterpret_cast<const int4*>(&g_A2[(size_t)(m0 + row) * KP + k0 + col]);
        }
        // B tile 32x128
        #pragma unroll
        for (int cch = tid; cch < 512; cch += 256) {
            int row = cch >> 4, col = (cch & 15) * 8;
            *reinterpret_cast<int4*>(&Bs[row * BLD + col]) =
                *reinterpret_cast<const int4*>(&g_B2[(size_t)(k0 + row) * VPAD + n0 + col]);
        }
        __syncthreads();

        #pragma unroll
        for (int ks = 0; ks < 2; ks++) {
            wmma::fragment<wmma::matrix_a, 16, 16, 16, __nv_bfloat16, wmma::row_major> af[2];
            wmma::fragment<wmma::matrix_b, 16, 16, 16, __nv_bfloat16, wmma::row_major> bf[4];
            #pragma unroll
            for (int i = 0; i < 2; i++)
                wmma::load_matrix_sync(af[i], &As[(wr * 32 + i * 16) * ALD + ks * 16], ALD);
            #pragma unroll
            for (int jn = 0; jn < 4; jn++)
                wmma::load_matrix_sync(bf[jn], &Bs[(ks * 16) * BLD + wc * 64 + jn * 16], BLD);
            #pragma unroll
            for (int i = 0; i < 2; i++)
                #pragma unroll
                for (int jn = 0; jn < 4; jn++)
                    wmma::mma_sync(acc[i][jn], af[i], bf[jn], acc[i][jn]);
        }
        __syncthreads();
    }

    // epilogue: stage through SMEM (bounds + bias)
    #pragma unroll
    for (int i = 0; i < 2; i++)
        #pragma unroll
        for (int jn = 0; jn < 4; jn++)
            wmma::store_matrix_sync(&Cs[(wr * 32 + i * 16) * CLD + wc * 64 + jn * 16],
                                    acc[i][jn], CLD, wmma::mem_row_major);
    __syncthreads();

    for (int idx = tid; idx < GBM * GBN; idx += 256) {
        int row = idx >> 7, col = idx & 127;
        int n = n0 + col;
        if (n < VV)
            out[(size_t)(m0 + row) * VV + n] = Cs[row * CLD + col] + bq[n];
    }
}

// ---------------- launch ----------------
extern "C" void kernel_launch(void* const* d_in, const int* in_sizes, int n_in,
                              void* d_out, int out_size) {
    const int*   x     = (const int*)  d_in[0];
    const float* state = (const float*)d_in[1];
    const float* cell  = (const float*)d_in[2];
    const float* W_xi  = (const float*)d_in[3];
    const float* W_hi  = (const float*)d_in[4];
    const float* b_i   = (const float*)d_in[5];
    const float* W_xf  = (const float*)d_in[6];
    const float* W_hf  = (const float*)d_in[7];
    const float* b_f   = (const float*)d_in[8];
    const float* W_xo  = (const float*)d_in[9];
    const float* W_ho  = (const float*)d_in[10];
    const float* b_o   = (const float*)d_in[11];
    const float* W_xc  = (const float*)d_in[12];
    const float* W_hc  = (const float*)d_in[13];
    const float* b_c   = (const float*)d_in[14];
    const float* W_hq  = (const float*)d_in[15];
    const float* b_q   = (const float*)d_in[16];
    float* out = (float*)d_out;

    // SMEM attrs (idempotent, capture-safe)
    size_t lstm_smem = (64 * WSTRIDE + 16 * 512 + 1024 + 256) * sizeof(float);
    cudaFuncSetAttribute(lstm_steps, cudaFuncAttributeMaxDynamicSharedMemorySize,
                         (int)lstm_smem);
    size_t gemm_smem = (size_t)GBM * CLD * sizeof(float);  // 67584 > load stage, reused
    cudaFuncSetAttribute(gemm_out, cudaFuncAttributeMaxDynamicSharedMemorySize,
                         (int)gemm_smem);

    // 1) transpose hidden weights
    build_wt<<<(4 * HH * HH + 255) / 256, 256>>>(W_hi, W_hf, W_ho, W_hc);
    // 2) split output weights into bf16 hi/lo (padded)
    build_b2<<<(KP * VPAD + 255) / 256, 256>>>(W_hq);
    // 3) sequential recurrence (persistent, grid barrier)
    lstm_steps<<<128, 256, lstm_smem>>>(x, state, cell,
                                        W_xi, W_xf, W_xo, W_xc,
                                        b_i, b_f, b_o, b_c, out);
    // 4) split hidden states into bf16 hi/lo
    build_a2<<<(TT * BB * KP + 255) / 256, 256>>>();
    // 5) big output GEMM + bias
    gemm_out<<<dim3(VPAD / GBN, (TT * BB) / GBM), 256, gemm_smem>>>(b_q, out);
}

// round 5
// speedup vs baseline: 1.1230x; 1.1230x over previous
#include <cuda_runtime.h>
#include <cuda_bf16.h>
#include <cstdint>

// ---------------- problem constants ----------------
#define TT   128      // seq len
#define BB   64       // batch
#define HH   512      // hidden
#define VV   10000    // vocab

// split-bf16 GEMM: C = Ahi@Bhi + Alo@Bhi + Ahi@Blo  (K' = 1536 logical)
// storage: A2 [8192][1024] = [hi(512)|lo(512)], B2T [10240][1024] = [hi|lo]
#define KSTORE 1024
#define TM     128
#define TN     256
#define TK     32
#define KTILES 48            // 1536 / 32 logical k-tiles
#define STAGES 4
#define MTILES (TT * BB / TM)   // 64
#define NTILES 40               // 40 * 256 = 10240
#define VPAD   (NTILES * TN)

#define A_ROW_B   80          // 64B data + 16B pad (ldmatrix conflict-free)
#define A_ST_B    (TM * A_ROW_B)    // 10240
#define B_ST_B    (TN * A_ROW_B)    // 20480
#define STAGE_B   (A_ST_B + B_ST_B) // 30720

// output layout: logits (T*B, V), then state (B,H), then cell (B,H)
#define OUT_STATE_OFF 81920000u
#define OUT_CELL_OFF  81952768u

// ---------------- device scratch ----------------
__device__ float   g_WT[4][HH][HH];
__device__ float   g_Hall[TT * BB * HH];
__device__ __align__(16) __nv_bfloat16 g_A2[(size_t)TT * BB * KSTORE];   // 16 MB
__device__ __align__(16) __nv_bfloat16 g_B2T[(size_t)VPAD * KSTORE];     // 20 MB
__device__ unsigned g_cnt = 0;
__device__ unsigned g_gen = 0;

__device__ __forceinline__ float sigmoidf_(float x) { return 1.0f / (1.0f + expf(-x)); }

__device__ __forceinline__ uint32_t smem_u32(const void* p) {
    uint32_t a;
    asm("{ .reg .u64 t; cvta.to.shared.u64 t, %1; cvt.u32.u64 %0, t; }" : "=r"(a) : "l"(p));
    return a;
}
__device__ __forceinline__ void cp_async16(uint32_t dst, const void* src) {
    asm volatile("cp.async.cg.shared.global [%0], [%1], 16;" :: "r"(dst), "l"(src));
}
__device__ __forceinline__ void ldsm_x4(uint32_t* r, uint32_t addr) {
    asm volatile("ldmatrix.sync.aligned.m8n8.x4.shared.b16 {%0,%1,%2,%3}, [%4];"
                 : "=r"(r[0]), "=r"(r[1]), "=r"(r[2]), "=r"(r[3]) : "r"(addr));
}
__device__ __forceinline__ void mma16816(float* c, const uint32_t* a, uint32_t b0, uint32_t b1) {
    asm volatile("mma.sync.aligned.m16n8k16.row.col.f32.bf16.bf16.f32 "
                 "{%0,%1,%2,%3}, {%4,%5,%6,%7}, {%8,%9}, {%0,%1,%2,%3};"
                 : "+f"(c[0]), "+f"(c[1]), "+f"(c[2]), "+f"(c[3])
                 : "r"(a[0]), "r"(a[1]), "r"(a[2]), "r"(a[3]), "r"(b0), "r"(b1));
}

// ---------------- prep: transpose the 4 hidden weight matrices ----------------
__global__ void build_wt(const float* __restrict__ Wi, const float* __restrict__ Wf,
                         const float* __restrict__ Wo, const float* __restrict__ Wc) {
    int idx = blockIdx.x * blockDim.x + threadIdx.x;
    if (idx >= 4 * HH * HH) return;
    int g = idx >> 18, rem = idx & 262143, j = rem >> 9, k = rem & 511;
    const float* W = (g == 0) ? Wi : (g == 1) ? Wf : (g == 2) ? Wo : Wc;
    g_WT[g][j][k] = W[k * HH + j];
}

// ---------------- prep: W_hq -> B^T bf16 [VPAD][1024] = [hi(512)|lo(512)] -----
// block (kc, nt): 64 k x 256 n tile; smem transpose then 16B writes.
__global__ void __launch_bounds__(256)
build_b2t(const float* __restrict__ Whq) {
    extern __shared__ float stile[];          // [64][257]
    const int kc = blockIdx.x;                // 0..7 (k chunk of 64)
    const int nt = blockIdx.y;                // 0..39
    const int tid = threadIdx.x;
    for (int idx = tid; idx < 64 * 256; idx += 256) {
        int kk = idx >> 8, nn = idx & 255;
        int n = nt * 256 + nn;
        stile[kk * 257 + nn] = (n < VV) ? Whq[(kc * 64 + kk) * VV + n] : 0.0f;
    }
    __syncthreads();
    for (int c = tid; c < 256 * 8; c += 256) {
        int row = c >> 3, ch = c & 7;         // row = local n, ch = 8-k chunk
        __nv_bfloat16 hv[8], lv[8];
        #pragma unroll
        for (int i = 0; i < 8; i++) {
            float w = stile[(ch * 8 + i) * 257 + row];
            __nv_bfloat16 hi = __float2bfloat16(w);
            hv[i] = hi;
            lv[i] = __float2bfloat16(w - __bfloat162float(hi));
        }
        size_t base = (size_t)(nt * 256 + row) * KSTORE + kc * 64 + ch * 8;
        *reinterpret_cast<int4*>(&g_B2T[base])       = *reinterpret_cast<int4*>(hv);
        *reinterpret_cast<int4*>(&g_B2T[base + 512]) = *reinterpret_cast<int4*>(lv);
    }
}

// ---------------- prep: g_Hall -> A bf16 [8192][1024] = [hi|lo] ---------------
__global__ void build_a2() {
    int idx = blockIdx.x * blockDim.x + threadIdx.x;   // one 16B (8 bf16) chunk
    if (idx >= TT * BB * (KSTORE / 8)) return;
    int m  = idx >> 7;            // /128 chunks per row
    int c8 = idx & 127;
    int kp = c8 * 8;
    int k  = kp & 511;
    const bool lo = (kp >= 512);
    const float* src = g_Hall + (size_t)m * HH + k;
    float4 f0 = *reinterpret_cast<const float4*>(src);
    float4 f1 = *reinterpret_cast<const float4*>(src + 4);
    float fv[8] = {f0.x, f0.y, f0.z, f0.w, f1.x, f1.y, f1.z, f1.w};
    __nv_bfloat16 v[8];
    #pragma unroll
    for (int i = 0; i < 8; i++) {
        __nv_bfloat16 hi = __float2bfloat16(fv[i]);
        v[i] = lo ? __float2bfloat16(fv[i] - __bfloat162float(hi)) : hi;
    }
    *reinterpret_cast<int4*>(&g_A2[(size_t)m * KSTORE + kp]) = *reinterpret_cast<int4*>(v);
}

// ---------------- persistent sequential LSTM recurrence (unchanged) ----------
#define WSTRIDE 516

__global__ void __launch_bounds__(256, 1)
lstm_steps(const int* __restrict__ x,
           const float* __restrict__ state0, const float* __restrict__ cell0,
           const float* __restrict__ Wxi, const float* __restrict__ Wxf,
           const float* __restrict__ Wxo, const float* __restrict__ Wxc,
           const float* __restrict__ bi,  const float* __restrict__ bf_,
           const float* __restrict__ bo,  const float* __restrict__ bc,
           float* __restrict__ out) {
    extern __shared__ float sm[];
    float* Wseg = sm;
    float* hbuf = Wseg + 64 * WSTRIDE;
    float* gbuf = hbuf + 16 * 512;
    float* cbuf = gbuf + 1024;

    const int tid = threadIdx.x;
    const int bt  = blockIdx.x & 3;
    const int hc  = blockIdx.x >> 2;
    const int c   = tid & 63;
    const int rg  = tid >> 6;
    const int g   = c >> 4;
    const int u   = c & 15;
    const int j   = hc * 16 + u;

    unsigned genBase = 0;
    if (tid == 0) genBase = *(volatile unsigned*)&g_gen;

    for (int idx = tid; idx < 64 * 512; idx += 256) {
        int cc = idx >> 9, kk = idx & 511;
        int gg = cc >> 4, uu = cc & 15;
        Wseg[cc * WSTRIDE + kk] = g_WT[gg][hc * 16 + uu][kk];
    }
    {
        int bl = tid >> 4, uu = tid & 15;
        cbuf[bl * 16 + uu] = cell0[(bt * 16 + bl) * HH + hc * 16 + uu];
    }
    const float* bptr = (g == 0) ? bi : (g == 1) ? bf_ : (g == 2) ? bo : bc;
    const float  bias = bptr[j];
    const float* Wx   = (g == 0) ? Wxi : (g == 1) ? Wxf : (g == 2) ? Wxo : Wxc;
    __syncthreads();

    for (int t = 0; t < TT; t++) {
        const float* hp = (t == 0) ? state0 : (g_Hall + (t - 1) * BB * HH);
        for (int idx = tid; idx < 16 * 512; idx += 256) {
            int bl = idx >> 9, kk = idx & 511;
            hbuf[bl * 512 + kk] = hp[(bt * 16 + bl) * HH + kk];
        }
        __syncthreads();

        float acc0 = 0.f, acc1 = 0.f, acc2 = 0.f, acc3 = 0.f;
        const float* wrow = Wseg + c * WSTRIDE;
        const float* h0 = hbuf + (rg * 4 + 0) * 512;
        const float* h1 = hbuf + (rg * 4 + 1) * 512;
        const float* h2 = hbuf + (rg * 4 + 2) * 512;
        const float* h3 = hbuf + (rg * 4 + 3) * 512;
        #pragma unroll 8
        for (int kk = 0; kk < 512; kk += 4) {
            float4 w = *reinterpret_cast<const float4*>(wrow + kk);
            float4 a = *reinterpret_cast<const float4*>(h0 + kk);
            acc0 = fmaf(w.x, a.x, acc0); acc0 = fmaf(w.y, a.y, acc0);
            acc0 = fmaf(w.z, a.z, acc0); acc0 = fmaf(w.w, a.w, acc0);
            a = *reinterpret_cast<const float4*>(h1 + kk);
            acc1 = fmaf(w.x, a.x, acc1); acc1 = fmaf(w.y, a.y, acc1);
            acc1 = fmaf(w.z, a.z, acc1); acc1 = fmaf(w.w, a.w, acc1);
            a = *reinterpret_cast<const float4*>(h2 + kk);
            acc2 = fmaf(w.x, a.x, acc2); acc2 = fmaf(w.y, a.y, acc2);
            acc2 = fmaf(w.z, a.z, acc2); acc2 = fmaf(w.w, a.w, acc2);
            a = *reinterpret_cast<const float4*>(h3 + kk);
            acc3 = fmaf(w.x, a.x, acc3); acc3 = fmaf(w.y, a.y, acc3);
            acc3 = fmaf(w.z, a.z, acc3); acc3 = fmaf(w.w, a.w, acc3);
        }

        float accs[4] = {acc0, acc1, acc2, acc3};
        #pragma unroll
        for (int r = 0; r < 4; r++) {
            int b   = bt * 16 + rg * 4 + r;
            int tok = x[b * TT + t];
            float pre = accs[r] + bias + Wx[tok * HH + j];
            float act = (g < 3) ? sigmoidf_(pre) : tanhf(pre);
            gbuf[g * 256 + (rg * 4 + r) * 16 + u] = act;
        }
        __syncthreads();

        {
            int bl = tid >> 4, uu = tid & 15;
            int o  = bl * 16 + uu;
            float iv = gbuf[o];
            float fv = gbuf[256 + o];
            float ov = gbuf[512 + o];
            float gv = gbuf[768 + o];
            float cn = fmaf(fv, cbuf[o], iv * gv);
            cbuf[o] = cn;
            float hn = ov * tanhf(cn);
            int brow = bt * 16 + bl, kcol = hc * 16 + uu;
            g_Hall[(t * BB + brow) * HH + kcol] = hn;
            if (t == TT - 1) {
                out[OUT_STATE_OFF + brow * HH + kcol] = hn;
                out[OUT_CELL_OFF  + brow * HH + kcol] = cn;
            }
        }
        __threadfence();
        __syncthreads();

        if (t < TT - 1) {
            if (tid == 0) {
                unsigned arr = atomicAdd(&g_cnt, 1u);
                if (arr == gridDim.x - 1) {
                    atomicExch(&g_cnt, 0u);
                    __threadfence();
                    atomicAdd(&g_gen, 1u);
                } else {
                    unsigned target = (unsigned)(t + 1);
                    while ((*(volatile unsigned*)&g_gen) - genBase < target)
                        __nanosleep(40);
                }
                __threadfence();
            }
            __syncthreads();
        }
    }
}

// ---------------- mma.sync output GEMM: out = A2 @ B2T^T + b_q ----------------
// grid (NTILES, MTILES); CTA 128x256; 8 warps as 2(M) x 4(N), warp tile 64x64.
__global__ void __launch_bounds__(256, 1)
gemm_mma(const float* __restrict__ bq, float* __restrict__ out) {
    extern __shared__ __align__(128) char dsm[];
    const uint32_t sbase = smem_u32(dsm);
    const int tid = threadIdx.x;
    const int wid = tid >> 5;
    const int lid = tid & 31;
    const int nt  = blockIdx.x;
    const int mt  = blockIdx.y;
    const int m0  = mt * TM;
    const int n0  = nt * TN;
    const int wm  = (wid >> 2) * 64;   // warp M offset (0/64)
    const int wn  = (wid & 3) * 64;    // warp N offset (0/64/128/192)

    const __nv_bfloat16* gA = g_A2  + (size_t)m0 * KSTORE;
    const __nv_bfloat16* gB = g_B2T + (size_t)n0 * KSTORE;

    // k-tile -> storage offsets (bf16 elements)
    auto a_off = [](int kt) { return ((kt < 32) ? kt : kt - 32) * TK; };
    auto b_off = [](int kt) { return ((kt < 16) ? kt : kt - 16) * TK; };

    float acc[4][8][4];
    #pragma unroll
    for (int i = 0; i < 4; i++)
        #pragma unroll
        for (int j = 0; j < 8; j++)
            #pragma unroll
            for (int q = 0; q < 4; q++) acc[i][j][q] = 0.0f;

    // issue loads for one k-tile into stage s
    auto load_stage = [&](int kt, int s) {
        uint32_t dA = sbase + s * STAGE_B;
        uint32_t dB = dA + A_ST_B;
        int ao = a_off(kt), bo = b_off(kt);
        #pragma unroll
        for (int c = 0; c < 2; c++) {                  // A: 512 chunks / 256 thr
            int ch = (c * 256 + tid);
            int row = ch >> 2, cc = ch & 3;
            cp_async16(dA + row * A_ROW_B + cc * 16,
                       gA + (size_t)row * KSTORE + ao + cc * 8);
        }
        #pragma unroll
        for (int c = 0; c < 4; c++) {                  // B: 1024 chunks
            int ch = (c * 256 + tid);
            int row = ch >> 2, cc = ch & 3;
            cp_async16(dB + row * A_ROW_B + cc * 16,
                       gB + (size_t)row * KSTORE + bo + cc * 8);
        }
        asm volatile("cp.async.commit_group;" ::: "memory");
    };

    #pragma unroll
    for (int s = 0; s < STAGES - 1; s++) load_stage(s, s);

    const int lr = lid & 15;        // ldmatrix row lane
    const int lc = (lid >> 4) * 16; // ldmatrix col byte offset

    for (int t = 0; t < KTILES; t++) {
        const int s = t & (STAGES - 1);
        if (t <= KTILES - 3)      asm volatile("cp.async.wait_group 2;" ::: "memory");
        else if (t == KTILES - 2) asm volatile("cp.async.wait_group 1;" ::: "memory");
        else                      asm volatile("cp.async.wait_group 0;" ::: "memory");
        __syncthreads();

        const int tn = t + STAGES - 1;
        if (tn < KTILES) load_stage(tn, tn & (STAGES - 1));

        const uint32_t Ab = sbase + s * STAGE_B;
        const uint32_t Bb = Ab + A_ST_B;
        #pragma unroll
        for (int ks = 0; ks < 2; ks++) {
            uint32_t af[4][4], bf[4][4];
            #pragma unroll
            for (int i = 0; i < 4; i++)
                ldsm_x4(af[i], Ab + (wm + i * 16 + lr) * A_ROW_B + ks * 32 + lc);
            #pragma unroll
            for (int j = 0; j < 4; j++)
                ldsm_x4(bf[j], Bb + (wn + j * 16 + lr) * A_ROW_B + ks * 32 + lc);
            #pragma unroll
            for (int i = 0; i < 4; i++)
                #pragma unroll
                for (int j = 0; j < 4; j++) {
                    mma16816(acc[i][2 * j],     af[i], bf[j][0], bf[j][2]);
                    mma16816(acc[i][2 * j + 1], af[i], bf[j][1], bf[j][3]);
                }
        }
        __syncthreads();
    }

    // epilogue: direct float2 stores with bias
    const int qr = lid >> 2;          // 0..7
    const int qc = (lid & 3) * 2;     // 0,2,4,6
    float2 bias2[8];
    #pragma unroll
    for (int j = 0; j < 8; j++) {
        int n = n0 + wn + j * 8 + qc;
        bias2[j].x = (n < VV)     ? bq[n]     : 0.0f;
        bias2[j].y = (n + 1 < VV) ? bq[n + 1] : 0.0f;
    }
    #pragma unroll
    for (int i = 0; i < 4; i++) {
        int mrow = m0 + wm + i * 16 + qr;
        #pragma unroll
        for (int j = 0; j < 8; j++) {
            int n = n0 + wn + j * 8 + qc;
            if (n < VV) {
                float2 v0 = {acc[i][j][0] + bias2[j].x, acc[i][j][1] + bias2[j].y};
                float2 v1 = {acc[i][j][2] + bias2[j].x, acc[i][j][3] + bias2[j].y};
                *reinterpret_cast<float2*>(out + (size_t)mrow * VV + n) = v0;
                *reinterpret_cast<float2*>(out + (size_t)(mrow + 8) * VV + n) = v1;
            }
        }
    }
}

// ---------------- launch ----------------
extern "C" void kernel_launch(void* const* d_in, const int* in_sizes, int n_in,
                              void* d_out, int out_size) {
    const int*   x     = (const int*)  d_in[0];
    const float* state = (const float*)d_in[1];
    const float* cell  = (const float*)d_in[2];
    const float* W_xi  = (const float*)d_in[3];
    const float* W_hi  = (const float*)d_in[4];
    const float* b_i   = (const float*)d_in[5];
    const float* W_xf  = (const float*)d_in[6];
    const float* W_hf  = (const float*)d_in[7];
    const float* b_f   = (const float*)d_in[8];
    const float* W_xo  = (const float*)d_in[9];
    const float* W_ho  = (const float*)d_in[10];
    const float* b_o   = (const float*)d_in[11];
    const float* W_xc  = (const float*)d_in[12];
    const float* W_hc  = (const float*)d_in[13];
    const float* b_c   = (const float*)d_in[14];
    const float* W_hq  = (const float*)d_in[15];
    const float* b_q   = (const float*)d_in[16];
    float* out = (float*)d_out;

    size_t lstm_smem = (64 * WSTRIDE + 16 * 512 + 1024 + 256) * sizeof(float);
    cudaFuncSetAttribute(lstm_steps, cudaFuncAttributeMaxDynamicSharedMemorySize,
                         (int)lstm_smem);
    size_t b2t_smem = 64 * 257 * sizeof(float);
    cudaFuncSetAttribute(build_b2t, cudaFuncAttributeMaxDynamicSharedMemorySize,
                         (int)b2t_smem);
    size_t gemm_smem = (size_t)STAGES * STAGE_B;   // 122880
    cudaFuncSetAttribute(gemm_mma, cudaFuncAttributeMaxDynamicSharedMemorySize,
                         (int)gemm_smem);

    build_wt<<<(4 * HH * HH + 255) / 256, 256>>>(W_hi, W_hf, W_ho, W_hc);
    build_b2t<<<dim3(8, NTILES), 256, b2t_smem>>>(W_hq);
    lstm_steps<<<128, 256, lstm_smem>>>(x, state, cell,
                                        W_xi, W_xf, W_xo, W_xc,
                                        b_i, b_f, b_o, b_c, out);
    build_a2<<<(TT * BB * (KSTORE / 8) + 255) / 256, 256>>>();
    gemm_mma<<<dim3(NTILES, MTILES), 256, gemm_smem>>>(b_q, out);
}

// round 6
// speedup vs baseline: 1.5313x; 1.3636x over previous
#include <cuda_runtime.h>
#include <cuda_bf16.h>
#include <cstdint>

typedef unsigned long long ull;

// ---------------- problem constants ----------------
#define TT   128      // seq len
#define BB   64       // batch
#define HH   512      // hidden
#define VV   10000    // vocab

// split-bf16 GEMM: C = Ahi@Bhi + Alo@Bhi + Ahi@Blo  (K' = 1536 logical)
#define KSTORE 1024
#define TM     128
#define TN     256
#define TK     32
#define KTILES 48
#define STAGES 4
#define MTILES (TT * BB / TM)   // 64
#define NTILES 40               // 40 * 256 = 10240
#define VPAD   (NTILES * TN)

#define A_ROW_B   80
#define A_ST_B    (TM * A_ROW_B)    // 10240
#define B_ST_B    (TN * A_ROW_B)    // 20480
#define STAGE_B   (A_ST_B + B_ST_B) // 30720

#define OUT_STATE_OFF 81920000u
#define OUT_CELL_OFF  81952768u

// ---------------- device scratch ----------------
__device__ float   g_WT[4][HH][HH];
__device__ float   g_Hall[TT * BB * HH];
__device__ __align__(16) __nv_bfloat16 g_A2[(size_t)TT * BB * KSTORE];   // 16 MB
__device__ __align__(16) __nv_bfloat16 g_B2T[(size_t)VPAD * KSTORE];     // 20 MB
__device__ unsigned g_cnt = 0;
__device__ unsigned g_gen = 0;

__device__ __forceinline__ float sigmoidf_(float x) { return 1.0f / (1.0f + expf(-x)); }

__device__ __forceinline__ uint32_t smem_u32(const void* p) {
    uint32_t a;
    asm("{ .reg .u64 t; cvta.to.shared.u64 t, %1; cvt.u32.u64 %0, t; }" : "=r"(a) : "l"(p));
    return a;
}
__device__ __forceinline__ void cp_async16(uint32_t dst, const void* src) {
    asm volatile("cp.async.cg.shared.global [%0], [%1], 16;" :: "r"(dst), "l"(src));
}
__device__ __forceinline__ void ldsm_x4(uint32_t* r, uint32_t addr) {
    asm volatile("ldmatrix.sync.aligned.m8n8.x4.shared.b16 {%0,%1,%2,%3}, [%4];"
                 : "=r"(r[0]), "=r"(r[1]), "=r"(r[2]), "=r"(r[3]) : "r"(addr));
}
__device__ __forceinline__ void mma16816(float* c, const uint32_t* a, uint32_t b0, uint32_t b1) {
    asm volatile("mma.sync.aligned.m16n8k16.row.col.f32.bf16.bf16.f32 "
                 "{%0,%1,%2,%3}, {%4,%5,%6,%7}, {%8,%9}, {%0,%1,%2,%3};"
                 : "+f"(c[0]), "+f"(c[1]), "+f"(c[2]), "+f"(c[3])
                 : "r"(a[0]), "r"(a[1]), "r"(a[2]), "r"(a[3]), "r"(b0), "r"(b1));
}

// packed f32x2 helpers (B300: FFMA2 reachable only via explicit PTX)
__device__ __forceinline__ ull pk2(float a, float b) {
    ull r; asm("mov.b64 %0, {%1, %2};" : "=l"(r) : "f"(a), "f"(b)); return r;
}
#define FMA2(acc, a, b) \
    asm("fma.rn.f32x2 %0, %1, %2, %0;" : "+l"(acc) : "l"(a), "l"(b))
__device__ __forceinline__ float hsum2(ull v) {
    float lo, hi; asm("mov.b64 {%0, %1}, %2;" : "=f"(lo), "=f"(hi) : "l"(v));
    return lo + hi;
}

// ---------------- prep: transpose the 4 hidden weight matrices ----------------
__global__ void build_wt(const float* __restrict__ Wi, const float* __restrict__ Wf,
                         const float* __restrict__ Wo, const float* __restrict__ Wc) {
    int idx = blockIdx.x * blockDim.x + threadIdx.x;
    if (idx >= 4 * HH * HH) return;
    int g = idx >> 18, rem = idx & 262143, j = rem >> 9, k = rem & 511;
    const float* W = (g == 0) ? Wi : (g == 1) ? Wf : (g == 2) ? Wo : Wc;
    g_WT[g][j][k] = W[k * HH + j];
}

// ---------------- prep: W_hq -> B^T bf16 [VPAD][1024] = [hi|lo] --------------
__global__ void __launch_bounds__(256)
build_b2t(const float* __restrict__ Whq) {
    extern __shared__ float stile[];          // [64][257]
    const int kc = blockIdx.x;
    const int nt = blockIdx.y;
    const int tid = threadIdx.x;
    for (int idx = tid; idx < 64 * 256; idx += 256) {
        int kk = idx >> 8, nn = idx & 255;
        int n = nt * 256 + nn;
        stile[kk * 257 + nn] = (n < VV) ? Whq[(kc * 64 + kk) * VV + n] : 0.0f;
    }
    __syncthreads();
    for (int c = tid; c < 256 * 8; c += 256) {
        int row = c >> 3, ch = c & 7;
        __nv_bfloat16 hv[8], lv[8];
        #pragma unroll
        for (int i = 0; i < 8; i++) {
            float w = stile[(ch * 8 + i) * 257 + row];
            __nv_bfloat16 hi = __float2bfloat16(w);
            hv[i] = hi;
            lv[i] = __float2bfloat16(w - __bfloat162float(hi));
        }
        size_t base = (size_t)(nt * 256 + row) * KSTORE + kc * 64 + ch * 8;
        *reinterpret_cast<int4*>(&g_B2T[base])       = *reinterpret_cast<int4*>(hv);
        *reinterpret_cast<int4*>(&g_B2T[base + 512]) = *reinterpret_cast<int4*>(lv);
    }
}

// ---------------- prep: g_Hall -> A bf16 [8192][1024] = [hi|lo] ---------------
__global__ void build_a2() {
    int idx = blockIdx.x * blockDim.x + threadIdx.x;
    if (idx >= TT * BB * (KSTORE / 8)) return;
    int m  = idx >> 7;
    int c8 = idx & 127;
    int kp = c8 * 8;
    int k  = kp & 511;
    const bool lo = (kp >= 512);
    const float* src = g_Hall + (size_t)m * HH + k;
    float4 f0 = *reinterpret_cast<const float4*>(src);
    float4 f1 = *reinterpret_cast<const float4*>(src + 4);
    float fv[8] = {f0.x, f0.y, f0.z, f0.w, f1.x, f1.y, f1.z, f1.w};
    __nv_bfloat16 v[8];
    #pragma unroll
    for (int i = 0; i < 8; i++) {
        __nv_bfloat16 hi = __float2bfloat16(fv[i]);
        v[i] = lo ? __float2bfloat16(fv[i] - __bfloat162float(hi)) : hi;
    }
    *reinterpret_cast<int4*>(&g_A2[(size_t)m * KSTORE + kp]) = *reinterpret_cast<int4*>(v);
}

// ---------------- persistent LSTM recurrence: weights in registers -----------
// grid 128 = (bt 0-3) x (hc 0-31). CTA: 16 batch rows x 64 gate-cols, K=512.
// compute role: tid = ks*16 + cg   (ks = 32-wide K slice, cg = 4-col group)
//   thread holds W[4 cols][32 k] = 64 f32x2 in REGISTERS for all 128 steps.
// partials reduced over 16 ks through padded smem (stride 17: 2-way max).
#define PART_RSTRIDE 1088   // 64 cols * 17

__global__ void __launch_bounds__(256, 1)
lstm_steps(const int* __restrict__ x,
           const float* __restrict__ state0, const float* __restrict__ cell0,
           const float* __restrict__ Wxi, const float* __restrict__ Wxf,
           const float* __restrict__ Wxo, const float* __restrict__ Wxc,
           const float* __restrict__ bi,  const float* __restrict__ bf_,
           const float* __restrict__ bo,  const float* __restrict__ bc,
           float* __restrict__ out) {
    extern __shared__ float smf[];
    float* part   = smf;                       // 16 * 1088
    float* gbuf   = part + 16 * PART_RSTRIDE;  // 1024
    float* cbuf   = gbuf + 1024;               // 256
    int*   tokbuf = (int*)(cbuf + 256);        // 16 * 128

    const int tid = threadIdx.x;
    const int bt  = blockIdx.x & 3;
    const int hc  = blockIdx.x >> 2;

    // compute role
    const int ks = tid >> 4;          // 0..15
    const int cg = tid & 15;          // 0..15 (4 cols each)
    const int k0 = ks * 32;
    const int gate = cg >> 2;

    // reduce role
    const int rr = tid >> 4;          // 0..15 batch-local row
    const int cq = tid & 15;          // 0..15 (4 cols each)
    const int gate2 = cq >> 2;
    const int ub = (cq & 3) * 4;
    const int jb = hc * 16 + ub;

    // stage tokens + cell
    for (int i = tid; i < 16 * TT; i += 256) {
        int r = i >> 7, t = i & 127;
        tokbuf[i] = x[(bt * 16 + r) * TT + t];
    }
    {
        int bl = tid >> 4, uu = tid & 15;
        cbuf[tid] = cell0[(bt * 16 + bl) * HH + hc * 16 + uu];
    }

    // weights -> registers (64 f32x2)
    ull w2[64];
    #pragma unroll
    for (int cc = 0; cc < 4; cc++) {
        int u = (cg & 3) * 4 + cc;
        const float* wp = &g_WT[gate][hc * 16 + u][k0];
        #pragma unroll
        for (int p = 0; p < 16; p++)
            w2[cc * 16 + p] = *reinterpret_cast<const ull*>(wp + 2 * p);
    }

    const float* bias_p = (gate2 == 0) ? bi : (gate2 == 1) ? bf_ : (gate2 == 2) ? bo : bc;
    const float4 bias4  = *reinterpret_cast<const float4*>(&bias_p[jb]);
    const float* Wx2    = (gate2 == 0) ? Wxi : (gate2 == 1) ? Wxf : (gate2 == 2) ? Wxo : Wxc;

    unsigned genBase = 0;
    if (tid == 0) genBase = *(volatile unsigned*)&g_gen;
    __syncthreads();

    for (int t = 0; t < TT; t++) {
        // ---- compute partials: 8 row-pairs ----
        const float* hp = (t == 0) ? (state0 + (size_t)(bt * 16) * HH)
                                   : (g_Hall + (size_t)((t - 1) * BB + bt * 16) * HH);
        #pragma unroll 1
        for (int rp = 0; rp < 8; rp++) {
            const float* h0 = hp + (size_t)(2 * rp) * HH + k0;
            const float* h1 = h0 + HH;
            ull hv0[16], hv1[16];
            #pragma unroll
            for (int q = 0; q < 8; q++) {
                float4 f = *reinterpret_cast<const float4*>(h0 + q * 4);
                hv0[2 * q]     = pk2(f.x, f.y);
                hv0[2 * q + 1] = pk2(f.z, f.w);
            }
            #pragma unroll
            for (int q = 0; q < 8; q++) {
                float4 f = *reinterpret_cast<const float4*>(h1 + q * 4);
                hv1[2 * q]     = pk2(f.x, f.y);
                hv1[2 * q + 1] = pk2(f.z, f.w);
            }
            ull a00 = 0, a01 = 0, a02 = 0, a03 = 0;
            ull a10 = 0, a11 = 0, a12 = 0, a13 = 0;
            #pragma unroll
            for (int p = 0; p < 16; p++) {
                ull h0p = hv0[p], h1p = hv1[p];
                FMA2(a00, w2[p],      h0p);
                FMA2(a01, w2[16 + p], h0p);
                FMA2(a02, w2[32 + p], h0p);
                FMA2(a03, w2[48 + p], h0p);
                FMA2(a10, w2[p],      h1p);
                FMA2(a11, w2[16 + p], h1p);
                FMA2(a12, w2[32 + p], h1p);
                FMA2(a13, w2[48 + p], h1p);
            }
            int b0 = (2 * rp) * PART_RSTRIDE + (cg * 4) * 17 + ks;
            part[b0]      = hsum2(a00);
            part[b0 + 17] = hsum2(a01);
            part[b0 + 34] = hsum2(a02);
            part[b0 + 51] = hsum2(a03);
            int b1 = b0 + PART_RSTRIDE;
            part[b1]      = hsum2(a10);
            part[b1 + 17] = hsum2(a11);
            part[b1 + 34] = hsum2(a12);
            part[b1 + 51] = hsum2(a13);
        }
        __syncthreads();

        // ---- reduce over 16 ks + bias + x-gather + activation ----
        {
            int tok = tokbuf[rr * TT + t];
            float4 wx = *reinterpret_cast<const float4*>(&Wx2[(size_t)tok * HH + jb]);
            float o[4];
            #pragma unroll
            for (int cc = 0; cc < 4; cc++) {
                const float* pp = &part[rr * PART_RSTRIDE + (cq * 4 + cc) * 17];
                float s0 = pp[0] + pp[1],   s1 = pp[2] + pp[3];
                float s2 = pp[4] + pp[5],   s3 = pp[6] + pp[7];
                float s4 = pp[8] + pp[9],   s5 = pp[10] + pp[11];
                float s6 = pp[12] + pp[13], s7 = pp[14] + pp[15];
                o[cc] = ((s0 + s1) + (s2 + s3)) + ((s4 + s5) + (s6 + s7));
            }
            float pre0 = o[0] + bias4.x + wx.x;
            float pre1 = o[1] + bias4.y + wx.y;
            float pre2 = o[2] + bias4.z + wx.z;
            float pre3 = o[3] + bias4.w + wx.w;
            float4 act;
            if (gate2 < 3) {
                act.x = sigmoidf_(pre0); act.y = sigmoidf_(pre1);
                act.z = sigmoidf_(pre2); act.w = sigmoidf_(pre3);
            } else {
                act.x = tanhf(pre0); act.y = tanhf(pre1);
                act.z = tanhf(pre2); act.w = tanhf(pre3);
            }
            *reinterpret_cast<float4*>(&gbuf[gate2 * 256 + rr * 16 + ub]) = act;
        }
        __syncthreads();

        // ---- c/h update ----
        {
            int bl = tid >> 4, uu = tid & 15;
            int o  = bl * 16 + uu;
            float iv = gbuf[o];
            float fv = gbuf[256 + o];
            float ov = gbuf[512 + o];
            float gv = gbuf[768 + o];
            float cn = fmaf(fv, cbuf[o], iv * gv);
            cbuf[o] = cn;
            float hn = ov * tanhf(cn);
            int brow = bt * 16 + bl, kcol = hc * 16 + uu;
            g_Hall[(size_t)(t * BB + brow) * HH + kcol] = hn;
            if (t == TT - 1) {
                out[OUT_STATE_OFF + brow * HH + kcol] = hn;
                out[OUT_CELL_OFF  + brow * HH + kcol] = cn;
            }
        }
        __threadfence();
        __syncthreads();

        // ---- software grid barrier ----
        if (t < TT - 1) {
            if (tid == 0) {
                unsigned arr = atomicAdd(&g_cnt, 1u);
                if (arr == gridDim.x - 1) {
                    atomicExch(&g_cnt, 0u);
                    __threadfence();
                    atomicAdd(&g_gen, 1u);
                } else {
                    unsigned target = (unsigned)(t + 1);
                    while ((*(volatile unsigned*)&g_gen) - genBase < target)
                        __nanosleep(40);
                }
                __threadfence();
            }
            __syncthreads();
        }
    }
}

// ---------------- mma.sync output GEMM (unchanged from round 5) ---------------
__global__ void __launch_bounds__(256, 1)
gemm_mma(const float* __restrict__ bq, float* __restrict__ out) {
    extern __shared__ __align__(128) char dsm[];
    const uint32_t sbase = smem_u32(dsm);
    const int tid = threadIdx.x;
    const int wid = tid >> 5;
    const int lid = tid & 31;
    const int nt  = blockIdx.x;
    const int mt  = blockIdx.y;
    const int m0  = mt * TM;
    const int n0  = nt * TN;
    const int wm  = (wid >> 2) * 64;
    const int wn  = (wid & 3) * 64;

    const __nv_bfloat16* gA = g_A2  + (size_t)m0 * KSTORE;
    const __nv_bfloat16* gB = g_B2T + (size_t)n0 * KSTORE;

    auto a_off = [](int kt) { return ((kt < 32) ? kt : kt - 32) * TK; };
    auto b_off = [](int kt) { return ((kt < 16) ? kt : kt - 16) * TK; };

    float acc[4][8][4];
    #pragma unroll
    for (int i = 0; i < 4; i++)
        #pragma unroll
        for (int j = 0; j < 8; j++)
            #pragma unroll
            for (int q = 0; q < 4; q++) acc[i][j][q] = 0.0f;

    auto load_stage = [&](int kt, int s) {
        uint32_t dA = sbase + s * STAGE_B;
        uint32_t dB = dA + A_ST_B;
        int ao = a_off(kt), bo = b_off(kt);
        #pragma unroll
        for (int c = 0; c < 2; c++) {
            int ch = (c * 256 + tid);
            int row = ch >> 2, cc = ch & 3;
            cp_async16(dA + row * A_ROW_B + cc * 16,
                       gA + (size_t)row * KSTORE + ao + cc * 8);
        }
        #pragma unroll
        for (int c = 0; c < 4; c++) {
            int ch = (c * 256 + tid);
            int row = ch >> 2, cc = ch & 3;
            cp_async16(dB + row * A_ROW_B + cc * 16,
                       gB + (size_t)row * KSTORE + bo + cc * 8);
        }
        asm volatile("cp.async.commit_group;" ::: "memory");
    };

    #pragma unroll
    for (int s = 0; s < STAGES - 1; s++) load_stage(s, s);

    const int lr = lid & 15;
    const int lc = (lid >> 4) * 16;

    for (int t = 0; t < KTILES; t++) {
        const int s = t & (STAGES - 1);
        if (t <= KTILES - 3)      asm volatile("cp.async.wait_group 2;" ::: "memory");
        else if (t == KTILES - 2) asm volatile("cp.async.wait_group 1;" ::: "memory");
        else                      asm volatile("cp.async.wait_group 0;" ::: "memory");
        __syncthreads();

        const int tn = t + STAGES - 1;
        if (tn < KTILES) load_stage(tn, tn & (STAGES - 1));

        const uint32_t Ab = sbase + s * STAGE_B;
        const uint32_t Bb = Ab + A_ST_B;
        #pragma unroll
        for (int ks2 = 0; ks2 < 2; ks2++) {
            uint32_t af[4][4], bf[4][4];
            #pragma unroll
            for (int i = 0; i < 4; i++)
                ldsm_x4(af[i], Ab + (wm + i * 16 + lr) * A_ROW_B + ks2 * 32 + lc);
            #pragma unroll
            for (int j = 0; j < 4; j++)
                ldsm_x4(bf[j], Bb + (wn + j * 16 + lr) * A_ROW_B + ks2 * 32 + lc);
            #pragma unroll
            for (int i = 0; i < 4; i++)
                #pragma unroll
                for (int j = 0; j < 4; j++) {
                    mma16816(acc[i][2 * j],     af[i], bf[j][0], bf[j][2]);
                    mma16816(acc[i][2 * j + 1], af[i], bf[j][1], bf[j][3]);
                }
        }
        __syncthreads();
    }

    const int qr = lid >> 2;
    const int qc = (lid & 3) * 2;
    float2 bias2[8];
    #pragma unroll
    for (int j = 0; j < 8; j++) {
        int n = n0 + wn + j * 8 + qc;
        bias2[j].x = (n < VV)     ? bq[n]     : 0.0f;
        bias2[j].y = (n + 1 < VV) ? bq[n + 1] : 0.0f;
    }
    #pragma unroll
    for (int i = 0; i < 4; i++) {
        int mrow = m0 + wm + i * 16 + qr;
        #pragma unroll
        for (int j = 0; j < 8; j++) {
            int n = n0 + wn + j * 8 + qc;
            if (n < VV) {
                float2 v0 = {acc[i][j][0] + bias2[j].x, acc[i][j][1] + bias2[j].y};
                float2 v1 = {acc[i][j][2] + bias2[j].x, acc[i][j][3] + bias2[j].y};
                *reinterpret_cast<float2*>(out + (size_t)mrow * VV + n) = v0;
                *reinterpret_cast<float2*>(out + (size_t)(mrow + 8) * VV + n) = v1;
            }
        }
    }
}

// ---------------- launch ----------------
extern "C" void kernel_launch(void* const* d_in, const int* in_sizes, int n_in,
                              void* d_out, int out_size) {
    const int*   x     = (const int*)  d_in[0];
    const float* state = (const float*)d_in[1];
    const float* cell  = (const float*)d_in[2];
    const float* W_xi  = (const float*)d_in[3];
    const float* W_hi  = (const float*)d_in[4];
    const float* b_i   = (const float*)d_in[5];
    const float* W_xf  = (const float*)d_in[6];
    const float* W_hf  = (const float*)d_in[7];
    const float* b_f   = (const float*)d_in[8];
    const float* W_xo  = (const float*)d_in[9];
    const float* W_ho  = (const float*)d_in[10];
    const float* b_o   = (const float*)d_in[11];
    const float* W_xc  = (const float*)d_in[12];
    const float* W_hc  = (const float*)d_in[13];
    const float* b_c   = (const float*)d_in[14];
    const float* W_hq  = (const float*)d_in[15];
    const float* b_q   = (const float*)d_in[16];
    float* out = (float*)d_out;

    size_t lstm_smem = (16 * PART_RSTRIDE + 1024 + 256 + 16 * TT) * sizeof(float);
    cudaFuncSetAttribute(lstm_steps, cudaFuncAttributeMaxDynamicSharedMemorySize,
                         (int)lstm_smem);
    size_t b2t_smem = 64 * 257 * sizeof(float);
    cudaFuncSetAttribute(build_b2t, cudaFuncAttributeMaxDynamicSharedMemorySize,
                         (int)b2t_smem);
    size_t gemm_smem = (size_t)STAGES * STAGE_B;
    cudaFuncSetAttribute(gemm_mma, cudaFuncAttributeMaxDynamicSharedMemorySize,
                         (int)gemm_smem);

    build_wt<<<(4 * HH * HH + 255) / 256, 256>>>(W_hi, W_hf, W_ho, W_hc);
    build_b2t<<<dim3(8, NTILES), 256, b2t_smem>>>(W_hq);
    lstm_steps<<<128, 256, lstm_smem>>>(x, state, cell,
                                        W_xi, W_xf, W_xo, W_xc,
                                        b_i, b_f, b_o, b_c, out);
    build_a2<<<(TT * BB * (KSTORE / 8) + 255) / 256, 256>>>();
    gemm_mma<<<dim3(NTILES, MTILES), 256, gemm_smem>>>(b_q, out);
}